// round 13
// baseline (speedup 1.0000x reference)
#include <cuda_runtime.h>
#include <cuda_fp16.h>
#include <cstdint>

// Problem dims (fixed per reference)
#define T_DIM 512
#define B_DIM 32
#define I_DIM 512
#define H_DIM 512
#define M_DIM (T_DIM * B_DIM)   // 16384
#define N_DIM (3 * H_DIM)       // 1536
#define K_DIM I_DIM             // 512

// ---------------------------------------------------------------------------
// Device scratch (no allocs allowed)
// ---------------------------------------------------------------------------
__device__ float  g_gx[(size_t)M_DIM * N_DIM];      // 100 MB
__device__ __half g_A [(size_t)M_DIM * K_DIM];      // 16 MB
__device__ __half g_B [(size_t)N_DIM * K_DIM];      // 1.5 MB
__device__ int    g_flag[128];                      // per-bm tile counters

// ---------------------------------------------------------------------------
// PTX helpers (baseline-PTX features only)
// ---------------------------------------------------------------------------
__device__ __forceinline__ uint32_t smem_u32(const void* p) {
    uint32_t a;
    asm("{ .reg .u64 t; cvta.to.shared.u64 t, %1; cvt.u32.u64 %0, t; }"
        : "=r"(a) : "l"(p));
    return a;
}
__device__ __forceinline__ void cpa16(uint32_t dst, const void* src) {
    asm volatile("cp.async.cg.shared.global [%0], [%1], 16;"
                 :: "r"(dst), "l"(src));
}
__device__ __forceinline__ void cpa_commit() {
    asm volatile("cp.async.commit_group;" ::: "memory");
}
template <int N>
__device__ __forceinline__ void cpa_wait() {
    asm volatile("cp.async.wait_group %0;" :: "n"(N) : "memory");
}
__device__ __forceinline__ void ldm4(uint32_t* r, uint32_t addr) {
    asm volatile("ldmatrix.sync.aligned.m8n8.x4.shared.b16 {%0,%1,%2,%3}, [%4];"
                 : "=r"(r[0]), "=r"(r[1]), "=r"(r[2]), "=r"(r[3]) : "r"(addr));
}
__device__ __forceinline__ void mma_f16(float* c, const uint32_t* a,
                                        const uint32_t* b) {
    asm volatile(
        "mma.sync.aligned.m16n8k16.row.col.f32.f16.f16.f32 "
        "{%0,%1,%2,%3}, {%4,%5,%6,%7}, {%8,%9}, {%0,%1,%2,%3};"
        : "+f"(c[0]), "+f"(c[1]), "+f"(c[2]), "+f"(c[3])
        : "r"(a[0]), "r"(a[1]), "r"(a[2]), "r"(a[3]), "r"(b[0]), "r"(b[1]));
}
__device__ __forceinline__ float ex2f(float x) {
    float y;
    asm("ex2.approx.f32 %0, %1;" : "=f"(y) : "f"(x));
    return y;
}
__device__ __forceinline__ float rcpf(float x) {
    float y;
    asm("rcp.approx.f32 %0, %1;" : "=f"(y) : "f"(x));
    return y;
}
__device__ __forceinline__ void bar_gemm() {
    asm volatile("bar.sync 1, 512;" ::: "memory");
}
__device__ __forceinline__ int ld_acq(const int* p) {
    int v;
    asm volatile("ld.acquire.gpu.global.b32 %0, [%1];" : "=r"(v) : "l"(p) : "memory");
    return v;
}
__device__ __forceinline__ void red_release_add(int* p) {
    asm volatile("red.release.gpu.global.add.s32 [%0], 1;" :: "l"(p) : "memory");
}
__device__ __forceinline__ void nsleep(unsigned ns) {
    asm volatile("nanosleep.u32 %0;" :: "r"(ns));
}

// ---------------------------------------------------------------------------
// Convert: fp32 -> fp16 for A and B in one kernel; also zeroes g_flag.
// ---------------------------------------------------------------------------
__device__ __forceinline__ ushort4 f4_to_h4(float4 v) {
    ushort4 o;
    __half a = __float2half_rn(v.x), b = __float2half_rn(v.y);
    __half c = __float2half_rn(v.z), d = __float2half_rn(v.w);
    o.x = *(unsigned short*)&a; o.y = *(unsigned short*)&b;
    o.z = *(unsigned short*)&c; o.w = *(unsigned short*)&d;
    return o;
}
#define NA4 ((M_DIM * K_DIM) / 4)   // 2097152
#define NB4 ((N_DIM * K_DIM) / 4)   // 196608

__global__ void convert_all(const float4* __restrict__ x,
                            const float4* __restrict__ w) {
    const int i = blockIdx.x * 256 + threadIdx.x;
    if (i < 128) g_flag[i] = 0;
    if (i < NA4) {
        reinterpret_cast<ushort4*>(g_A)[i] = f4_to_h4(__ldcs(x + i));
    } else if (i < NA4 + NB4) {
        reinterpret_cast<ushort4*>(g_B)[i - NA4] = f4_to_h4(__ldcs(w + (i - NA4)));
    }
}

// ---------------------------------------------------------------------------
// Persistent fused GEMM + scan kernel. SINGLE WAVE BY CONSTRUCTION:
// 128 CTAs x 576 threads, 96 KB smem -> 1 CTA/SM, all CTAs resident at once
// (no cross-wave dependency -> no deadlock; GEMM never waits on scan).
// Warps 0-15: 6 GEMM tile-jobs each (job = cta + wave*128 -> tiles complete
// in bm order), continuous cp.async pipeline across jobs.
// Warps 16-17: scan, 2 chains/thread, gated per 4-timestep tile on g_flag.
// ---------------------------------------------------------------------------
#define GBM 128
#define GBN 256
#define GBK 32
#define NCTA 128
#define NJOBS 768                   // 128 bm x 6 bn
#define JOBS_PER_CTA 6
#define GKTOT (JOBS_PER_CTA * 16)   // 96 pipeline steps per CTA
#define NSTAGE 4
#define ROWB 64                     // smem row stride (32 fp16)
#define SA_BYTES (128 * ROWB)       // 8192
#define SB_BYTES (256 * ROWB)       // 16384
#define STAGE_BYTES (SA_BYTES + SB_BYTES)           // 24576
#define OFF_A 0
#define OFF_B SA_BYTES
#define GEMM_SMEM (NSTAGE * STAGE_BYTES)            // 98304

__device__ __forceinline__ uint32_t swz_off(int row, int u) {
    return (uint32_t)(row * ROWB + ((u ^ ((row >> 1) & 3)) << 4));
}

__device__ __forceinline__ void load_stage_g(uint32_t sb, int gk, int cta, int tid) {
    const int job = cta + (gk >> 4) * NCTA;
    const int mbase = (job / 6) * GBM;
    const int nbase = (job % 6) * GBN;
    const int k0 = (gk & 15) * GBK;
    const uint32_t dst = sb + (gk & 3) * STAGE_BYTES;
    {
        int row = tid >> 2, u = tid & 3;
        cpa16(dst + OFF_A + swz_off(row, u),
              g_A + (size_t)(mbase + row) * K_DIM + k0 + u * 8);
    }
#pragma unroll
    for (int j = 0; j < 2; ++j) {
        int unit = tid + j * 512;
        int row = unit >> 2, u = unit & 3;
        cpa16(dst + OFF_B + swz_off(row, u),
              g_B + (size_t)(nbase + row) * K_DIM + k0 + u * 8);
    }
    cpa_commit();
}

// ---- scan side ----
#define C_NL2E (-1.44269504088896f)   // -log2 e
#define C_2L2E (2.88539008177793f)    // 2 log2 e
#define SCAN_PF 4

struct Chain {
    float hv, nwr, nwz, wn2;
    const float* gbase;
    float* op;
    float bgr[SCAN_PF], bgz[SCAN_PF], bgn[SCAN_PF];
};

__device__ __forceinline__ void chain_init(Chain& ch, int sidx,
                                           const float* __restrict__ h0,
                                           const float* __restrict__ w_hh,
                                           float* __restrict__ out) {
    const int b = sidx >> 9;
    const int h = sidx & (H_DIM - 1);
    ch.nwr = C_NL2E * w_hh[h];
    ch.nwz = C_NL2E * w_hh[H_DIM + h];
    ch.wn2 = C_2L2E * w_hh[2 * H_DIM + h];
    ch.hv  = h0[sidx];
    ch.gbase = g_gx + (size_t)b * N_DIM + h;
    ch.op = out + sidx;
}

__device__ __forceinline__ void chain_prefetch(Chain& ch, int t, int s) {
    const float* gp = ch.gbase + (size_t)t * (B_DIM * N_DIM);
    ch.bgr[s] = __ldcs(gp);
    ch.bgz[s] = __ldcs(gp + H_DIM);
    ch.bgn[s] = __ldcs(gp + 2 * H_DIM);
}

__device__ __forceinline__ void chain_step(Chain& ch, int t, int s) {
    const float gr = ch.bgr[s], gz = ch.bgz[s], gn = ch.bgn[s];
    const float ngr = C_NL2E * gr;
    const float ngz = C_NL2E * gz;
    const float gn2 = C_2L2E * gn;
    const float hv = ch.hv;
    const float er = ex2f(fmaf(ch.nwr, hv, ngr));
    const float r  = rcpf(1.f + er);
    const float ez = ex2f(fmaf(ch.nwz, hv, ngz));
    const float z  = rcpf(1.f + ez);
    const float wnh2 = ch.wn2 * hv;
    const float e2 = ex2f(fmaf(r, wnh2, gn2));
    const float n  = fmaf(-2.f, rcpf(1.f + e2), 1.f);
    ch.hv = fmaf(z, hv - n, n);
    __stcs(ch.op + (size_t)t * (B_DIM * H_DIM), ch.hv);
}

__global__ __launch_bounds__(576, 1)
void indgru_fused(const float* __restrict__ h0, const float* __restrict__ w_hh,
                  float* __restrict__ out) {
    const int tid = threadIdx.x;
    const int wid = tid >> 5;
    const int cta = blockIdx.x;

    if (wid >= 16) {
        // ---- scan warps: 2 per CTA; 8192 threads x 2 chains ----
        const int sidx = cta * 64 + (wid - 16) * 32 + (tid & 31);  // 0..8191
        Chain a, b;
        chain_init(a, sidx, h0, w_hh, out);
        chain_init(b, sidx + 8192, h0, w_hh, out);

        int ready = 0;
#define ENSURE_TILE(tile)                                                  \
        if ((tile) >= ready) {                                             \
            while (ld_acq(g_flag + (tile)) != 6) nsleep(128);              \
            ready = (tile) + 1;                                            \
        }

#pragma unroll
        for (int i = 0; i < SCAN_PF; ++i) {
            ENSURE_TILE(i >> 2);
            chain_prefetch(a, i, i);
            chain_prefetch(b, i, i);
        }
        for (int t = 0; t < T_DIM; ++t) {
            const int s = t & (SCAN_PF - 1);
            const int tp = t + SCAN_PF;
            // consume first (data for t already resident), then refill slot
            chain_step(a, t, s);
            chain_step(b, t, s);
            if (tp < T_DIM) {
                ENSURE_TILE(tp >> 2);
                chain_prefetch(a, tp, s);
                chain_prefetch(b, tp, s);
            }
        }
        __stcs(a.op + (size_t)T_DIM * (B_DIM * H_DIM), a.hv);
        __stcs(b.op + (size_t)T_DIM * (B_DIM * H_DIM), b.hv);
#undef ENSURE_TILE
        return;
    }

    // ---- GEMM warps 0-15 (512 threads): 6 jobs, continuous pipeline ----
    extern __shared__ __align__(128) char smem[];
    const uint32_t sb = smem_u32(smem);
    const int lid = tid & 31;

    const int m_warp = (wid >> 3) * 64;    // 0 or 64
    const int n_warp = (wid & 7) * 32;     // 0..224

    const int rowA = m_warp + (lid & 7) + ((lid >> 3) & 1) * 8;
    const int uA = (lid >> 4) & 1;               // + ks*2
    const int rowBm = n_warp + (lid & 7) + ((lid >> 4) & 1) * 8;
    const int uB = (lid >> 3) & 1;               // + ks*2

    float c[4][4][4];

    load_stage_g(sb, 0, cta, tid);
    load_stage_g(sb, 1, cta, tid);
    load_stage_g(sb, 2, cta, tid);

    for (int gk = 0; gk < GKTOT; ++gk) {
        const int kt = gk & 15;
        if (kt == 0) {
#pragma unroll
            for (int i = 0; i < 4; ++i)
#pragma unroll
                for (int j = 0; j < 4; ++j)
#pragma unroll
                    for (int q = 0; q < 4; ++q) c[i][j][q] = 0.f;
        }

        // drain exactly so the group for stage gk is complete before use
        if (gk < GKTOT - 2)      cpa_wait<2>();
        else if (gk == GKTOT - 2) cpa_wait<1>();
        else                      cpa_wait<0>();
        bar_gemm();   // stage gk ready for all; stage gk-1 fully consumed

        if (gk + 3 < GKTOT) load_stage_g(sb, gk + 3, cta, tid);

        const uint32_t st = sb + (gk & 3) * STAGE_BYTES;
#pragma unroll
        for (int ks = 0; ks < 2; ++ks) {
            uint32_t Ah[4][4], Bf[2][4];
#pragma unroll
            for (int mf = 0; mf < 4; ++mf)
                ldm4(Ah[mf], st + OFF_A + swz_off(rowA + mf * 16, uA + ks * 2));
#pragma unroll
            for (int nfp = 0; nfp < 2; ++nfp)
                ldm4(Bf[nfp], st + OFF_B + swz_off(rowBm + nfp * 16, uB + ks * 2));
#pragma unroll
            for (int mf = 0; mf < 4; ++mf)
#pragma unroll
                for (int nfp = 0; nfp < 2; ++nfp)
#pragma unroll
                    for (int hf = 0; hf < 2; ++hf)
                        mma_f16(c[mf][nfp * 2 + hf], Ah[mf], &Bf[nfp][hf * 2]);
        }

        if (kt == 15) {
            const int job = cta + (gk >> 4) * NCTA;
            const int mbase = (job / 6) * GBM;
            const int nbase = (job % 6) * GBN;
            const int g = lid >> 2, t4 = lid & 3;
#pragma unroll
            for (int mf = 0; mf < 4; ++mf) {
                const int m0 = mbase + m_warp + mf * 16 + g;
                float* r0 = g_gx + (size_t)m0 * N_DIM + nbase + n_warp;
                float* r1 = r0 + (size_t)8 * N_DIM;
#pragma unroll
                for (int nf = 0; nf < 4; ++nf) {
                    const int nc = nf * 8 + 2 * t4;
                    *reinterpret_cast<float2*>(r0 + nc) =
                        make_float2(c[mf][nf][0], c[mf][nf][1]);
                    *reinterpret_cast<float2*>(r1 + nc) =
                        make_float2(c[mf][nf][2], c[mf][nf][3]);
                }
            }
            __threadfence();
            bar_gemm();
            if (tid == 0) red_release_add(g_flag + job / 6);
        }
    }
}

// ---------------------------------------------------------------------------
extern "C" void kernel_launch(void* const* d_in, const int* in_sizes, int n_in,
                              void* d_out, int out_size) {
    const float* x    = (const float*)d_in[0];   // (T, B, I)
    const float* h0   = (const float*)d_in[1];   // (B, H)
    const float* W_ih = (const float*)d_in[2];   // (3H, I)
    const float* w_hh = (const float*)d_in[3];   // (3, H)
    float* out = (float*)d_out;

    convert_all<<<(NA4 + NB4 + 255) / 256, 256>>>((const float4*)x,
                                                  (const float4*)W_ih);

    cudaFuncSetAttribute(indgru_fused,
                         cudaFuncAttributeMaxDynamicSharedMemorySize, GEMM_SMEM);
    indgru_fused<<<NCTA, 576, GEMM_SMEM>>>(h0, w_hh, out);
}

// round 15
// speedup vs baseline: 1.8750x; 1.8750x over previous
#include <cuda_runtime.h>
#include <cuda_fp16.h>
#include <cstdint>

// Problem dims (fixed per reference)
#define T_DIM 512
#define B_DIM 32
#define I_DIM 512
#define H_DIM 512
#define M_DIM (T_DIM * B_DIM)   // 16384
#define N_DIM (3 * H_DIM)       // 1536
#define K_DIM I_DIM             // 512

// ---------------------------------------------------------------------------
// Device scratch (no allocs allowed)
// ---------------------------------------------------------------------------
__device__ __half g_gx[(size_t)M_DIM * N_DIM];      // 50 MB (fits in L2!)
__device__ __half g_A [(size_t)M_DIM * K_DIM];      // 16 MB
__device__ __half g_B [(size_t)N_DIM * K_DIM];      // 1.5 MB

// ---------------------------------------------------------------------------
// PTX helpers (baseline-PTX features only: cp.async, ldmatrix, mma.sync)
// ---------------------------------------------------------------------------
__device__ __forceinline__ uint32_t smem_u32(const void* p) {
    uint32_t a;
    asm("{ .reg .u64 t; cvta.to.shared.u64 t, %1; cvt.u32.u64 %0, t; }"
        : "=r"(a) : "l"(p));
    return a;
}
__device__ __forceinline__ void cpa16(uint32_t dst, const void* src) {
    asm volatile("cp.async.cg.shared.global [%0], [%1], 16;"
                 :: "r"(dst), "l"(src));
}
__device__ __forceinline__ void cpa_commit() {
    asm volatile("cp.async.commit_group;" ::: "memory");
}
template <int N>
__device__ __forceinline__ void cpa_wait() {
    asm volatile("cp.async.wait_group %0;" :: "n"(N) : "memory");
}
__device__ __forceinline__ void ldm4(uint32_t* r, uint32_t addr) {
    asm volatile("ldmatrix.sync.aligned.m8n8.x4.shared.b16 {%0,%1,%2,%3}, [%4];"
                 : "=r"(r[0]), "=r"(r[1]), "=r"(r[2]), "=r"(r[3]) : "r"(addr));
}
__device__ __forceinline__ void mma_f16(float* c, const uint32_t* a,
                                        const uint32_t* b) {
    asm volatile(
        "mma.sync.aligned.m16n8k16.row.col.f32.f16.f16.f32 "
        "{%0,%1,%2,%3}, {%4,%5,%6,%7}, {%8,%9}, {%0,%1,%2,%3};"
        : "+f"(c[0]), "+f"(c[1]), "+f"(c[2]), "+f"(c[3])
        : "r"(a[0]), "r"(a[1]), "r"(a[2]), "r"(a[3]), "r"(b[0]), "r"(b[1]));
}
__device__ __forceinline__ float ex2f(float x) {
    float y;
    asm("ex2.approx.f32 %0, %1;" : "=f"(y) : "f"(x));
    return y;
}
__device__ __forceinline__ float rcpf(float x) {
    float y;
    asm("rcp.approx.f32 %0, %1;" : "=f"(y) : "f"(x));
    return y;
}

// ---------------------------------------------------------------------------
// Converts: fp32 -> fp16 stream
// ---------------------------------------------------------------------------
__device__ __forceinline__ ushort4 f4_to_h4(float4 v) {
    ushort4 o;
    __half a = __float2half_rn(v.x), b = __float2half_rn(v.y);
    __half c = __float2half_rn(v.z), d = __float2half_rn(v.w);
    o.x = *(unsigned short*)&a; o.y = *(unsigned short*)&b;
    o.z = *(unsigned short*)&c; o.w = *(unsigned short*)&d;
    return o;
}
#define NA4 ((M_DIM * K_DIM) / 4)   // 2097152
#define NB4 ((N_DIM * K_DIM) / 4)   // 196608

__global__ void convert_all(const float4* __restrict__ x,
                            const float4* __restrict__ w) {
    const int i = blockIdx.x * 256 + threadIdx.x;
    if (i < NA4) {
        reinterpret_cast<ushort4*>(g_A)[i] = f4_to_h4(__ldcs(x + i));
    } else if (i < NA4 + NB4) {
        reinterpret_cast<ushort4*>(g_B)[i - NA4] = f4_to_h4(__ldcs(w + (i - NA4)));
    }
}

// ---------------------------------------------------------------------------
// HMMA GEMM: gx = A . B^T, fp16 x fp16 -> fp32 accum -> fp16 store.
// CTA 128x256, 512 threads (16 warps, warp 64x32), BK=32,
// 4-stage cp.async ring, one __syncthreads per stage.
// Smem rows 64 B, XOR swizzle u' = u ^ ((row>>1)&3) -> conflict-free ldmatrix.
// ---------------------------------------------------------------------------
#define GBM 128
#define GBN 256
#define GBK 32
#define NSTEPS (K_DIM / GBK)        // 16
#define NSTAGE 4
#define ROWB 64                     // smem row stride (32 fp16)
#define SA_BYTES (128 * ROWB)       // 8192
#define SB_BYTES (256 * ROWB)       // 16384
#define STAGE_BYTES (SA_BYTES + SB_BYTES)           // 24576
#define OFF_A 0
#define OFF_B SA_BYTES
#define GEMM_SMEM (NSTAGE * STAGE_BYTES)            // 98304

__device__ __forceinline__ uint32_t swz_off(int row, int u) {
    return (uint32_t)(row * ROWB + ((u ^ ((row >> 1) & 3)) << 4));
}

__device__ __forceinline__ void load_stage(uint32_t sb, int stage, int kt,
                                           int mbase, int nbase, int tid) {
    const int k0 = kt * GBK;
    const uint32_t dst = sb + stage * STAGE_BYTES;
    {
        int row = tid >> 2, u = tid & 3;
        cpa16(dst + OFF_A + swz_off(row, u),
              g_A + (size_t)(mbase + row) * K_DIM + k0 + u * 8);
    }
#pragma unroll
    for (int j = 0; j < 2; ++j) {
        int unit = tid + j * 512;
        int row = unit >> 2, u = unit & 3;
        cpa16(dst + OFF_B + swz_off(row, u),
              g_B + (size_t)(nbase + row) * K_DIM + k0 + u * 8);
    }
    cpa_commit();
}

__global__ __launch_bounds__(512) void indgru_gemm_mma() {
    extern __shared__ __align__(128) char smem[];
    const uint32_t sb = smem_u32(smem);
    const int tid = threadIdx.x;
    const int wid = tid >> 5;
    const int lid = tid & 31;
    const int mbase = blockIdx.x * GBM;
    const int nbase = blockIdx.y * GBN;

    const int m_warp = (wid >> 3) * 64;    // 0 or 64
    const int n_warp = (wid & 7) * 32;     // 0..224

    const int rowA = m_warp + (lid & 7) + ((lid >> 3) & 1) * 8;
    const int uA = (lid >> 4) & 1;               // + ks*2
    const int rowBm = n_warp + (lid & 7) + ((lid >> 4) & 1) * 8;
    const int uB = (lid >> 3) & 1;               // + ks*2

    float c[4][4][4];
#pragma unroll
    for (int i = 0; i < 4; ++i)
#pragma unroll
        for (int j = 0; j < 4; ++j)
#pragma unroll
            for (int q = 0; q < 4; ++q) c[i][j][q] = 0.f;

    load_stage(sb, 0, 0, mbase, nbase, tid);
    load_stage(sb, 1, 1, mbase, nbase, tid);
    load_stage(sb, 2, 2, mbase, nbase, tid);

    for (int kt = 0; kt < NSTEPS; ++kt) {
        const int stage = kt & (NSTAGE - 1);
        if (kt < NSTEPS - 3)      cpa_wait<2>();
        else if (kt == NSTEPS - 3) cpa_wait<2>();
        else if (kt == NSTEPS - 2) cpa_wait<1>();
        else                       cpa_wait<0>();
        __syncthreads();   // stage kt ready; stage kt-1 fully consumed

        if (kt + 3 < NSTEPS)
            load_stage(sb, (kt + 3) & (NSTAGE - 1), kt + 3, mbase, nbase, tid);

        const uint32_t st = sb + stage * STAGE_BYTES;
#pragma unroll
        for (int ks = 0; ks < 2; ++ks) {
            uint32_t Ah[4][4], Bf[2][4];
#pragma unroll
            for (int mf = 0; mf < 4; ++mf)
                ldm4(Ah[mf], st + OFF_A + swz_off(rowA + mf * 16, uA + ks * 2));
#pragma unroll
            for (int nfp = 0; nfp < 2; ++nfp)
                ldm4(Bf[nfp], st + OFF_B + swz_off(rowBm + nfp * 16, uB + ks * 2));
#pragma unroll
            for (int mf = 0; mf < 4; ++mf)
#pragma unroll
                for (int nfp = 0; nfp < 2; ++nfp)
#pragma unroll
                    for (int hf = 0; hf < 2; ++hf)
                        mma_f16(c[mf][nfp * 2 + hf], Ah[mf], &Bf[nfp][hf * 2]);
        }
    }

    // epilogue: c[mf][nf] -> g_gx (fp16, default caching -> stays in L2)
    const int g = lid >> 2, t4 = lid & 3;
#pragma unroll
    for (int mf = 0; mf < 4; ++mf) {
        const int m0 = mbase + m_warp + mf * 16 + g;
        __half* r0 = g_gx + (size_t)m0 * N_DIM + nbase + n_warp;
        __half* r1 = r0 + (size_t)8 * N_DIM;
#pragma unroll
        for (int nf = 0; nf < 4; ++nf) {
            const int nc = nf * 8 + 2 * t4;
            *reinterpret_cast<__half2*>(r0 + nc) =
                __floats2half2_rn(c[mf][nf][0], c[mf][nf][1]);
            *reinterpret_cast<__half2*>(r1 + nc) =
                __floats2half2_rn(c[mf][nf][2], c[mf][nf][3]);
        }
    }
}

// ---------------------------------------------------------------------------
// Scan: one thread per (b, h); 512 blocks x 32 threads. Depth-16 raw-ushort
// prefetch ring (gx is fp16 and L2-resident right after the GEMM -> ~240 cyc
// hits, fully hidden). H2F conversion at consume time, off the load path.
// ---------------------------------------------------------------------------
#define C_NL2E (-1.44269504088896f)   // -log2 e
#define C_2L2E (2.88539008177793f)    // 2 log2 e
#define SCAN_PF 16

__device__ __forceinline__ float us2f(unsigned short u) {
    __half_raw hr; hr.x = u;
    return __half2float(__half(hr));
}

__global__ __launch_bounds__(32)
void indgru_scan(const float* __restrict__ h0, const float* __restrict__ w_hh,
                 float* __restrict__ out) {
    const int idx = blockIdx.x * 32 + threadIdx.x;    // 0..16383
    const int b = idx >> 9;
    const int h = idx & (H_DIM - 1);

    const float nwr = C_NL2E * w_hh[h];
    const float nwz = C_NL2E * w_hh[H_DIM + h];
    const float wn2 = C_2L2E * w_hh[2 * H_DIM + h];

    float hv = h0[idx];

    const unsigned short* gbase =
        reinterpret_cast<const unsigned short*>(g_gx) + (size_t)b * N_DIM + h;
    const int TSTRIDE = B_DIM * N_DIM;                // 49152 (halves)

    unsigned short bgr[SCAN_PF], bgz[SCAN_PF], bgn[SCAN_PF];   // raw fp16 bits
#pragma unroll
    for (int i = 0; i < SCAN_PF; ++i) {
        const unsigned short* gp = gbase + (size_t)i * TSTRIDE;
        bgr[i] = gp[0];
        bgz[i] = gp[H_DIM];
        bgn[i] = gp[2 * H_DIM];
    }

    float* op = out + idx;

#pragma unroll 16
    for (int t = 0; t < T_DIM; ++t) {
        const int s = t & (SCAN_PF - 1);
        const unsigned short ur = bgr[s], uz = bgz[s], un = bgn[s];

        const int tp = t + SCAN_PF;
        if (tp < T_DIM) {
            const unsigned short* gp = gbase + (size_t)tp * TSTRIDE;
            bgr[s] = gp[0];
            bgz[s] = gp[H_DIM];
            bgn[s] = gp[2 * H_DIM];
        }

        // convert + scale at consume time (data long-arrived, off load path)
        const float ngr = C_NL2E * us2f(ur);
        const float ngz = C_NL2E * us2f(uz);
        const float gn2 = C_2L2E * us2f(un);

        const float er = ex2f(fmaf(nwr, hv, ngr));
        const float r  = rcpf(1.f + er);
        const float ez = ex2f(fmaf(nwz, hv, ngz));
        const float z  = rcpf(1.f + ez);
        const float wnh2 = wn2 * hv;                  // off-chain vs r
        const float e2 = ex2f(fmaf(r, wnh2, gn2));
        const float n  = fmaf(-2.f, rcpf(1.f + e2), 1.f);
        hv = fmaf(z, hv - n, n);

        __stcs(op + (size_t)t * (B_DIM * H_DIM), hv);
    }
    __stcs(op + (size_t)T_DIM * (B_DIM * H_DIM), hv);
}

// ---------------------------------------------------------------------------
extern "C" void kernel_launch(void* const* d_in, const int* in_sizes, int n_in,
                              void* d_out, int out_size) {
    const float* x    = (const float*)d_in[0];   // (T, B, I)
    const float* h0   = (const float*)d_in[1];   // (B, H)
    const float* W_ih = (const float*)d_in[2];   // (3H, I)
    const float* w_hh = (const float*)d_in[3];   // (3, H)
    float* out = (float*)d_out;

    convert_all<<<(NA4 + NB4 + 255) / 256, 256>>>((const float4*)x,
                                                  (const float4*)W_ih);

    cudaFuncSetAttribute(indgru_gemm_mma,
                         cudaFuncAttributeMaxDynamicSharedMemorySize, GEMM_SMEM);
    dim3 grid(M_DIM / GBM, N_DIM / GBN);   // 128 x 6
    indgru_gemm_mma<<<grid, 512, GEMM_SMEM>>>();

    indgru_scan<<<(B_DIM * H_DIM) / 32, 32>>>(h0, w_hh, out);
}

// round 16
// speedup vs baseline: 2.4085x; 1.2845x over previous
#include <cuda_runtime.h>
#include <cuda_fp16.h>
#include <cstdint>

// Problem dims (fixed per reference)
#define T_DIM 512
#define B_DIM 32
#define I_DIM 512
#define H_DIM 512
#define M_DIM (T_DIM * B_DIM)   // 16384
#define N_DIM (3 * H_DIM)       // 1536
#define K_DIM I_DIM             // 512

// ---------------------------------------------------------------------------
// Device scratch (no allocs allowed)
// ---------------------------------------------------------------------------
__device__ __half g_gx[(size_t)M_DIM * N_DIM];      // 50 MB (fits in L2)
__device__ __half g_A [(size_t)M_DIM * K_DIM];      // 16 MB
__device__ __half g_B [(size_t)N_DIM * K_DIM];      // 1.5 MB

// ---------------------------------------------------------------------------
// PTX helpers (baseline-PTX features only: cp.async, ldmatrix, mma.sync)
// ---------------------------------------------------------------------------
__device__ __forceinline__ uint32_t smem_u32(const void* p) {
    uint32_t a;
    asm("{ .reg .u64 t; cvta.to.shared.u64 t, %1; cvt.u32.u64 %0, t; }"
        : "=r"(a) : "l"(p));
    return a;
}
__device__ __forceinline__ void cpa16(uint32_t dst, const void* src) {
    asm volatile("cp.async.cg.shared.global [%0], [%1], 16;"
                 :: "r"(dst), "l"(src));
}
__device__ __forceinline__ void cpa_commit() {
    asm volatile("cp.async.commit_group;" ::: "memory");
}
template <int N>
__device__ __forceinline__ void cpa_wait() {
    asm volatile("cp.async.wait_group %0;" :: "n"(N) : "memory");
}
__device__ __forceinline__ void ldm4(uint32_t* r, uint32_t addr) {
    asm volatile("ldmatrix.sync.aligned.m8n8.x4.shared.b16 {%0,%1,%2,%3}, [%4];"
                 : "=r"(r[0]), "=r"(r[1]), "=r"(r[2]), "=r"(r[3]) : "r"(addr));
}
__device__ __forceinline__ void mma_f16(float* c, const uint32_t* a,
                                        const uint32_t* b) {
    asm volatile(
        "mma.sync.aligned.m16n8k16.row.col.f32.f16.f16.f32 "
        "{%0,%1,%2,%3}, {%4,%5,%6,%7}, {%8,%9}, {%0,%1,%2,%3};"
        : "+f"(c[0]), "+f"(c[1]), "+f"(c[2]), "+f"(c[3])
        : "r"(a[0]), "r"(a[1]), "r"(a[2]), "r"(a[3]), "r"(b[0]), "r"(b[1]));
}
__device__ __forceinline__ float ex2f(float x) {
    float y;
    asm("ex2.approx.f32 %0, %1;" : "=f"(y) : "f"(x));
    return y;
}
__device__ __forceinline__ float rcpf(float x) {
    float y;
    asm("rcp.approx.f32 %0, %1;" : "=f"(y) : "f"(x));
    return y;
}
__device__ __forceinline__ float tanhf_a(float x) {
    float y;
    asm("tanh.approx.f32 %0, %1;" : "=f"(y) : "f"(x));
    return y;
}

// ---------------------------------------------------------------------------
// Converts: fp32 -> fp16 stream
// ---------------------------------------------------------------------------
__device__ __forceinline__ ushort4 f4_to_h4(float4 v) {
    ushort4 o;
    __half a = __float2half_rn(v.x), b = __float2half_rn(v.y);
    __half c = __float2half_rn(v.z), d = __float2half_rn(v.w);
    o.x = *(unsigned short*)&a; o.y = *(unsigned short*)&b;
    o.z = *(unsigned short*)&c; o.w = *(unsigned short*)&d;
    return o;
}
#define NA4 ((M_DIM * K_DIM) / 4)   // 2097152
#define NB4 ((N_DIM * K_DIM) / 4)   // 196608

__global__ void convert_all(const float4* __restrict__ x,
                            const float4* __restrict__ w) {
    const int i = blockIdx.x * 256 + threadIdx.x;
    if (i < NA4) {
        reinterpret_cast<ushort4*>(g_A)[i] = f4_to_h4(__ldcs(x + i));
    } else if (i < NA4 + NB4) {
        reinterpret_cast<ushort4*>(g_B)[i - NA4] = f4_to_h4(__ldcs(w + (i - NA4)));
    }
}

// ---------------------------------------------------------------------------
// HMMA GEMM: gx = A . B^T, fp16 -> fp32 accum -> fp16 store.
// CTA 128x128, 256 threads (8 warps 2x4, warp tile 64x32), BK=32,
// 4-stage cp.async ring, 64 KB smem -> 2 CTAs/SM co-resident.
// Smem rows 64 B, XOR swizzle u' = u ^ ((row>>1)&3) -> conflict-free ldmatrix.
// ---------------------------------------------------------------------------
#define GBM 128
#define GBN 128
#define GBK 32
#define NSTEPS (K_DIM / GBK)        // 16
#define NSTAGE 4
#define ROWB 64                     // smem row stride (32 fp16)
#define SA_BYTES (128 * ROWB)       // 8192
#define SB_BYTES (128 * ROWB)       // 8192
#define STAGE_BYTES (SA_BYTES + SB_BYTES)           // 16384
#define OFF_A 0
#define OFF_B SA_BYTES
#define GEMM_SMEM (NSTAGE * STAGE_BYTES)            // 65536

__device__ __forceinline__ uint32_t swz_off(int row, int u) {
    return (uint32_t)(row * ROWB + ((u ^ ((row >> 1) & 3)) << 4));
}

__device__ __forceinline__ void load_stage(uint32_t sb, int stage, int kt,
                                           int mbase, int nbase, int tid) {
    const int k0 = kt * GBK;
    const uint32_t dst = sb + stage * STAGE_BYTES;
    // A and B: 128 rows x 4 16B-units = 512 ops each; 256 threads -> 2 each
#pragma unroll
    for (int j = 0; j < 2; ++j) {
        int unit = tid + j * 256;
        int row = unit >> 2, u = unit & 3;
        uint32_t o = swz_off(row, u);
        cpa16(dst + OFF_A + o, g_A + (size_t)(mbase + row) * K_DIM + k0 + u * 8);
        cpa16(dst + OFF_B + o, g_B + (size_t)(nbase + row) * K_DIM + k0 + u * 8);
    }
    cpa_commit();
}

__global__ __launch_bounds__(256, 2) void indgru_gemm_mma() {
    extern __shared__ __align__(128) char smem[];
    const uint32_t sb = smem_u32(smem);
    const int tid = threadIdx.x;
    const int wid = tid >> 5;
    const int lid = tid & 31;
    const int mbase = blockIdx.x * GBM;
    const int nbase = blockIdx.y * GBN;

    const int m_warp = (wid >> 2) * 64;    // 0 or 64
    const int n_warp = (wid & 3) * 32;     // 0..96

    const int rowA = m_warp + (lid & 7) + ((lid >> 3) & 1) * 8;
    const int uA = (lid >> 4) & 1;               // + ks*2
    const int rowBm = n_warp + (lid & 7) + ((lid >> 4) & 1) * 8;
    const int uB = (lid >> 3) & 1;               // + ks*2

    float c[4][4][4];
#pragma unroll
    for (int i = 0; i < 4; ++i)
#pragma unroll
        for (int j = 0; j < 4; ++j)
#pragma unroll
            for (int q = 0; q < 4; ++q) c[i][j][q] = 0.f;

    load_stage(sb, 0, 0, mbase, nbase, tid);
    load_stage(sb, 1, 1, mbase, nbase, tid);
    load_stage(sb, 2, 2, mbase, nbase, tid);

    for (int kt = 0; kt < NSTEPS; ++kt) {
        const int stage = kt & (NSTAGE - 1);
        if (kt < NSTEPS - 2)       cpa_wait<2>();
        else if (kt == NSTEPS - 2) cpa_wait<1>();
        else                       cpa_wait<0>();
        __syncthreads();   // stage kt ready; stage kt-1 fully consumed

        if (kt + 3 < NSTEPS)
            load_stage(sb, (kt + 3) & (NSTAGE - 1), kt + 3, mbase, nbase, tid);

        const uint32_t st = sb + stage * STAGE_BYTES;
#pragma unroll
        for (int ks = 0; ks < 2; ++ks) {
            uint32_t Ah[4][4], Bf[2][4];
#pragma unroll
            for (int mf = 0; mf < 4; ++mf)
                ldm4(Ah[mf], st + OFF_A + swz_off(rowA + mf * 16, uA + ks * 2));
#pragma unroll
            for (int nfp = 0; nfp < 2; ++nfp)
                ldm4(Bf[nfp], st + OFF_B + swz_off(rowBm + nfp * 16, uB + ks * 2));
#pragma unroll
            for (int mf = 0; mf < 4; ++mf)
#pragma unroll
                for (int nfp = 0; nfp < 2; ++nfp)
#pragma unroll
                    for (int hf = 0; hf < 2; ++hf)
                        mma_f16(c[mf][nfp * 2 + hf], Ah[mf], &Bf[nfp][hf * 2]);
        }
    }

    // epilogue: c[mf][nf] -> g_gx (fp16, default caching -> stays in L2)
    const int g = lid >> 2, t4 = lid & 3;
#pragma unroll
    for (int mf = 0; mf < 4; ++mf) {
        const int m0 = mbase + m_warp + mf * 16 + g;
        __half* r0 = g_gx + (size_t)m0 * N_DIM + nbase + n_warp;
        __half* r1 = r0 + (size_t)8 * N_DIM;
#pragma unroll
        for (int nf = 0; nf < 4; ++nf) {
            const int nc = nf * 8 + 2 * t4;
            *reinterpret_cast<__half2*>(r0 + nc) =
                __floats2half2_rn(c[mf][nf][0], c[mf][nf][1]);
            *reinterpret_cast<__half2*>(r1 + nc) =
                __floats2half2_rn(c[mf][nf][2], c[mf][nf][3]);
        }
    }
}

// ---------------------------------------------------------------------------
// Scan: one thread per (b, h); 512 blocks x 32 threads. Depth-16 raw-ushort
// prefetch ring (gx fp16, L2-resident). Gate math: r, z via tanh.approx
// (sigmoid(x) = 0.5 tanh(x/2) + 0.5, 24-cyc path); n via precise ex2/rcp.
// ---------------------------------------------------------------------------
#define C_2L2E (2.88539008177793f)    // 2 log2 e
#define SCAN_PF 16

__device__ __forceinline__ float us2f(unsigned short u) {
    __half_raw hr; hr.x = u;
    return __half2float(__half(hr));
}

__global__ __launch_bounds__(32)
void indgru_scan(const float* __restrict__ h0, const float* __restrict__ w_hh,
                 float* __restrict__ out) {
    const int idx = blockIdx.x * 32 + threadIdx.x;    // 0..16383
    const int b = idx >> 9;
    const int h = idx & (H_DIM - 1);

    const float hwr = 0.5f * w_hh[h];                 // half-scaled for tanh form
    const float hwz = 0.5f * w_hh[H_DIM + h];
    const float wn2 = C_2L2E * w_hh[2 * H_DIM + h];

    float hv = h0[idx];

    const unsigned short* gbase =
        reinterpret_cast<const unsigned short*>(g_gx) + (size_t)b * N_DIM + h;
    const int TSTRIDE = B_DIM * N_DIM;                // 49152 (halves)

    unsigned short bgr[SCAN_PF], bgz[SCAN_PF], bgn[SCAN_PF];   // raw fp16 bits
#pragma unroll
    for (int i = 0; i < SCAN_PF; ++i) {
        const unsigned short* gp = gbase + (size_t)i * TSTRIDE;
        bgr[i] = gp[0];
        bgz[i] = gp[H_DIM];
        bgn[i] = gp[2 * H_DIM];
    }

    float* op = out + idx;

#pragma unroll 16
    for (int t = 0; t < T_DIM; ++t) {
        const int s = t & (SCAN_PF - 1);
        const unsigned short ur = bgr[s], uz = bgz[s], un = bgn[s];

        const int tp = t + SCAN_PF;
        if (tp < T_DIM) {
            const unsigned short* gp = gbase + (size_t)tp * TSTRIDE;
            bgr[s] = gp[0];
            bgz[s] = gp[H_DIM];
            bgn[s] = gp[2 * H_DIM];
        }

        // convert + scale at consume time (off the load path)
        const float hgr = 0.5f * us2f(ur);
        const float hgz = 0.5f * us2f(uz);
        const float gn2 = C_2L2E * us2f(un);

        // r = sigmoid(gr + wr h) = 0.5 tanh(0.5(gr + wr h)) + 0.5
        const float r = fmaf(0.5f, tanhf_a(fmaf(hwr, hv, hgr)), 0.5f);
        const float z = fmaf(0.5f, tanhf_a(fmaf(hwz, hv, hgz)), 0.5f);
        // n = tanh(gn + r wn h) via precise ex2/rcp (output-critical)
        const float wnh2 = wn2 * hv;                  // off-chain vs r
        const float e2 = ex2f(fmaf(r, wnh2, gn2));
        const float n  = fmaf(-2.f, rcpf(1.f + e2), 1.f);
        hv = fmaf(z, hv - n, n);

        __stcs(op + (size_t)t * (B_DIM * H_DIM), hv);
    }
    __stcs(op + (size_t)T_DIM * (B_DIM * H_DIM), hv);
}

// ---------------------------------------------------------------------------
extern "C" void kernel_launch(void* const* d_in, const int* in_sizes, int n_in,
                              void* d_out, int out_size) {
    const float* x    = (const float*)d_in[0];   // (T, B, I)
    const float* h0   = (const float*)d_in[1];   // (B, H)
    const float* W_ih = (const float*)d_in[2];   // (3H, I)
    const float* w_hh = (const float*)d_in[3];   // (3, H)
    float* out = (float*)d_out;

    convert_all<<<(NA4 + NB4 + 255) / 256, 256>>>((const float4*)x,
                                                  (const float4*)W_ih);

    cudaFuncSetAttribute(indgru_gemm_mma,
                         cudaFuncAttributeMaxDynamicSharedMemorySize, GEMM_SMEM);
    dim3 grid(M_DIM / GBM, N_DIM / GBN);   // 128 x 12
    indgru_gemm_mma<<<grid, 256, GEMM_SMEM>>>();

    indgru_scan<<<(B_DIM * H_DIM) / 32, 32>>>(h0, w_hh, out);
}

// round 17
// speedup vs baseline: 2.5931x; 1.0766x over previous
#include <cuda_runtime.h>
#include <cuda_fp16.h>
#include <cstdint>

// Problem dims (fixed per reference)
#define T_DIM 512
#define B_DIM 32
#define I_DIM 512
#define H_DIM 512
#define M_DIM (T_DIM * B_DIM)   // 16384
#define N_DIM (3 * H_DIM)       // 1536
#define K_DIM I_DIM             // 512

// ---------------------------------------------------------------------------
// Device scratch (no allocs allowed)
// ---------------------------------------------------------------------------
__device__ __half g_gx[(size_t)M_DIM * N_DIM];      // 50 MB
__device__ __half g_A [(size_t)M_DIM * K_DIM];      // 16 MB
__device__ __half g_B [(size_t)N_DIM * K_DIM];      // 1.5 MB

// ---------------------------------------------------------------------------
// PTX helpers (baseline-PTX features only: cp.async, ldmatrix, mma.sync)
// ---------------------------------------------------------------------------
__device__ __forceinline__ uint32_t smem_u32(const void* p) {
    uint32_t a;
    asm("{ .reg .u64 t; cvta.to.shared.u64 t, %1; cvt.u32.u64 %0, t; }"
        : "=r"(a) : "l"(p));
    return a;
}
__device__ __forceinline__ void cpa16(uint32_t dst, const void* src) {
    asm volatile("cp.async.cg.shared.global [%0], [%1], 16;"
                 :: "r"(dst), "l"(src));
}
__device__ __forceinline__ void cpa_commit() {
    asm volatile("cp.async.commit_group;" ::: "memory");
}
template <int N>
__device__ __forceinline__ void cpa_wait() {
    asm volatile("cp.async.wait_group %0;" :: "n"(N) : "memory");
}
__device__ __forceinline__ void ldm4(uint32_t* r, uint32_t addr) {
    asm volatile("ldmatrix.sync.aligned.m8n8.x4.shared.b16 {%0,%1,%2,%3}, [%4];"
                 : "=r"(r[0]), "=r"(r[1]), "=r"(r[2]), "=r"(r[3]) : "r"(addr));
}
__device__ __forceinline__ void mma_f16(float* c, const uint32_t* a,
                                        const uint32_t* b) {
    asm volatile(
        "mma.sync.aligned.m16n8k16.row.col.f32.f16.f16.f32 "
        "{%0,%1,%2,%3}, {%4,%5,%6,%7}, {%8,%9}, {%0,%1,%2,%3};"
        : "+f"(c[0]), "+f"(c[1]), "+f"(c[2]), "+f"(c[3])
        : "r"(a[0]), "r"(a[1]), "r"(a[2]), "r"(a[3]), "r"(b[0]), "r"(b[1]));
}
__device__ __forceinline__ float tanhf_a(float x) {
    float y;
    asm("tanh.approx.f32 %0, %1;" : "=f"(y) : "f"(x));
    return y;
}

// ---------------------------------------------------------------------------
// Converts: fp32 -> fp16 stream
// ---------------------------------------------------------------------------
__device__ __forceinline__ ushort4 f4_to_h4(float4 v) {
    ushort4 o;
    __half a = __float2half_rn(v.x), b = __float2half_rn(v.y);
    __half c = __float2half_rn(v.z), d = __float2half_rn(v.w);
    o.x = *(unsigned short*)&a; o.y = *(unsigned short*)&b;
    o.z = *(unsigned short*)&c; o.w = *(unsigned short*)&d;
    return o;
}
#define NA4 ((M_DIM * K_DIM) / 4)   // 2097152
#define NB4 ((N_DIM * K_DIM) / 4)   // 196608

__global__ void convert_all(const float4* __restrict__ x,
                            const float4* __restrict__ w) {
    const int i = blockIdx.x * 256 + threadIdx.x;
    if (i < NA4) {
        reinterpret_cast<ushort4*>(g_A)[i] = f4_to_h4(__ldcs(x + i));
    } else if (i < NA4 + NB4) {
        reinterpret_cast<ushort4*>(g_B)[i - NA4] = f4_to_h4(__ldcs(w + (i - NA4)));
    }
}

// ---------------------------------------------------------------------------
// HMMA GEMM: gx = A . B^T, fp16 -> fp32 accum -> fp16 store.
// CTA 128x128, 256 threads (8 warps 2x4, warp tile 64x32), BK=32,
// 4-stage cp.async ring, 64 KB smem -> 2 CTAs/SM co-resident.
// bm REVERSED vs launch order: earliest-t gx tiles are written LAST so they
// are L2-resident when the scan (which consumes t ascending) starts.
// ---------------------------------------------------------------------------
#define GBM 128
#define GBN 128
#define GBK 32
#define NSTEPS (K_DIM / GBK)        // 16
#define NSTAGE 4
#define ROWB 64                     // smem row stride (32 fp16)
#define SA_BYTES (128 * ROWB)       // 8192
#define SB_BYTES (128 * ROWB)       // 8192
#define STAGE_BYTES (SA_BYTES + SB_BYTES)           // 16384
#define OFF_A 0
#define OFF_B SA_BYTES
#define GEMM_SMEM (NSTAGE * STAGE_BYTES)            // 65536

__device__ __forceinline__ uint32_t swz_off(int row, int u) {
    return (uint32_t)(row * ROWB + ((u ^ ((row >> 1) & 3)) << 4));
}

__device__ __forceinline__ void load_stage(uint32_t sb, int stage, int kt,
                                           int mbase, int nbase, int tid) {
    const int k0 = kt * GBK;
    const uint32_t dst = sb + stage * STAGE_BYTES;
#pragma unroll
    for (int j = 0; j < 2; ++j) {
        int unit = tid + j * 256;
        int row = unit >> 2, u = unit & 3;
        uint32_t o = swz_off(row, u);
        cpa16(dst + OFF_A + o, g_A + (size_t)(mbase + row) * K_DIM + k0 + u * 8);
        cpa16(dst + OFF_B + o, g_B + (size_t)(nbase + row) * K_DIM + k0 + u * 8);
    }
    cpa_commit();
}

__global__ __launch_bounds__(256, 2) void indgru_gemm_mma() {
    extern __shared__ __align__(128) char smem[];
    const uint32_t sb = smem_u32(smem);
    const int tid = threadIdx.x;
    const int wid = tid >> 5;
    const int lid = tid & 31;
    const int mbase = (gridDim.x - 1 - blockIdx.x) * GBM;   // reversed bm
    const int nbase = blockIdx.y * GBN;

    const int m_warp = (wid >> 2) * 64;    // 0 or 64
    const int n_warp = (wid & 3) * 32;     // 0..96

    const int rowA = m_warp + (lid & 7) + ((lid >> 3) & 1) * 8;
    const int uA = (lid >> 4) & 1;               // + ks*2
    const int rowBm = n_warp + (lid & 7) + ((lid >> 4) & 1) * 8;
    const int uB = (lid >> 3) & 1;               // + ks*2

    float c[4][4][4];
#pragma unroll
    for (int i = 0; i < 4; ++i)
#pragma unroll
        for (int j = 0; j < 4; ++j)
#pragma unroll
            for (int q = 0; q < 4; ++q) c[i][j][q] = 0.f;

    load_stage(sb, 0, 0, mbase, nbase, tid);
    load_stage(sb, 1, 1, mbase, nbase, tid);
    load_stage(sb, 2, 2, mbase, nbase, tid);

    for (int kt = 0; kt < NSTEPS; ++kt) {
        const int stage = kt & (NSTAGE - 1);
        if (kt < NSTEPS - 2)       cpa_wait<2>();
        else if (kt == NSTEPS - 2) cpa_wait<1>();
        else                       cpa_wait<0>();
        __syncthreads();   // stage kt ready; stage kt-1 fully consumed

        if (kt + 3 < NSTEPS)
            load_stage(sb, (kt + 3) & (NSTAGE - 1), kt + 3, mbase, nbase, tid);

        const uint32_t st = sb + stage * STAGE_BYTES;
#pragma unroll
        for (int ks = 0; ks < 2; ++ks) {
            uint32_t Ah[4][4], Bf[2][4];
#pragma unroll
            for (int mf = 0; mf < 4; ++mf)
                ldm4(Ah[mf], st + OFF_A + swz_off(rowA + mf * 16, uA + ks * 2));
#pragma unroll
            for (int nfp = 0; nfp < 2; ++nfp)
                ldm4(Bf[nfp], st + OFF_B + swz_off(rowBm + nfp * 16, uB + ks * 2));
#pragma unroll
            for (int mf = 0; mf < 4; ++mf)
#pragma unroll
                for (int nfp = 0; nfp < 2; ++nfp)
#pragma unroll
                    for (int hf = 0; hf < 2; ++hf)
                        mma_f16(c[mf][nfp * 2 + hf], Ah[mf], &Bf[nfp][hf * 2]);
        }
    }

    // epilogue: c[mf][nf] -> g_gx (fp16, default caching -> stays in L2)
    const int g = lid >> 2, t4 = lid & 3;
#pragma unroll
    for (int mf = 0; mf < 4; ++mf) {
        const int m0 = mbase + m_warp + mf * 16 + g;
        __half* r0 = g_gx + (size_t)m0 * N_DIM + nbase + n_warp;
        __half* r1 = r0 + (size_t)8 * N_DIM;
#pragma unroll
        for (int nf = 0; nf < 4; ++nf) {
            const int nc = nf * 8 + 2 * t4;
            *reinterpret_cast<__half2*>(r0 + nc) =
                __floats2half2_rn(c[mf][nf][0], c[mf][nf][1]);
            *reinterpret_cast<__half2*>(r1 + nc) =
                __floats2half2_rn(c[mf][nf][2], c[mf][nf][3]);
        }
    }
}

// ---------------------------------------------------------------------------
// Scan: one thread per (b, h); 512 blocks x 32 threads. Depth-16 raw-ushort
// prefetch ring. All three gates via tanh.approx:
//   sigmoid(x) = 0.5 tanh(0.5 x) + 0.5 ; n = tanh(gn + r wn h) directly.
// Critical chain: fma->tanh->fma (r) -> fma->tanh (n) -> sub->fma  ~52 cyc.
// ---------------------------------------------------------------------------
#define SCAN_PF 16

__device__ __forceinline__ float us2f(unsigned short u) {
    __half_raw hr; hr.x = u;
    return __half2float(__half(hr));
}

__global__ __launch_bounds__(32)
void indgru_scan(const float* __restrict__ h0, const float* __restrict__ w_hh,
                 float* __restrict__ out) {
    const int idx = blockIdx.x * 32 + threadIdx.x;    // 0..16383
    const int b = idx >> 9;
    const int h = idx & (H_DIM - 1);

    const float hwr = 0.5f * w_hh[h];                 // half-scaled (sigmoid-as-tanh)
    const float hwz = 0.5f * w_hh[H_DIM + h];
    const float wn  = w_hh[2 * H_DIM + h];

    float hv = h0[idx];

    const unsigned short* gbase =
        reinterpret_cast<const unsigned short*>(g_gx) + (size_t)b * N_DIM + h;
    const int TSTRIDE = B_DIM * N_DIM;                // 49152 (halves)

    unsigned short bgr[SCAN_PF], bgz[SCAN_PF], bgn[SCAN_PF];   // raw fp16 bits
#pragma unroll
    for (int i = 0; i < SCAN_PF; ++i) {
        const unsigned short* gp = gbase + (size_t)i * TSTRIDE;
        bgr[i] = gp[0];
        bgz[i] = gp[H_DIM];
        bgn[i] = gp[2 * H_DIM];
    }

    float* op = out + idx;

#pragma unroll 16
    for (int t = 0; t < T_DIM; ++t) {
        const int s = t & (SCAN_PF - 1);
        const unsigned short ur = bgr[s], uz = bgz[s], un = bgn[s];

        const int tp = t + SCAN_PF;
        if (tp < T_DIM) {
            const unsigned short* gp = gbase + (size_t)tp * TSTRIDE;
            bgr[s] = gp[0];
            bgz[s] = gp[H_DIM];
            bgn[s] = gp[2 * H_DIM];
        }

        // convert + scale at consume time (off the load path)
        const float hgr = 0.5f * us2f(ur);
        const float hgz = 0.5f * us2f(uz);
        const float gnf = us2f(un);

        const float r = fmaf(0.5f, tanhf_a(fmaf(hwr, hv, hgr)), 0.5f);
        const float z = fmaf(0.5f, tanhf_a(fmaf(hwz, hv, hgz)), 0.5f);
        const float wnh = wn * hv;                    // off-chain vs r
        const float n = tanhf_a(fmaf(r, wnh, gnf));
        hv = fmaf(z, hv - n, n);

        __stcs(op + (size_t)t * (B_DIM * H_DIM), hv);
    }
    __stcs(op + (size_t)T_DIM * (B_DIM * H_DIM), hv);
}

// ---------------------------------------------------------------------------
extern "C" void kernel_launch(void* const* d_in, const int* in_sizes, int n_in,
                              void* d_out, int out_size) {
    const float* x    = (const float*)d_in[0];   // (T, B, I)
    const float* h0   = (const float*)d_in[1];   // (B, H)
    const float* W_ih = (const float*)d_in[2];   // (3H, I)
    const float* w_hh = (const float*)d_in[3];   // (3, H)
    float* out = (float*)d_out;

    convert_all<<<(NA4 + NB4 + 255) / 256, 256>>>((const float4*)x,
                                                  (const float4*)W_ih);

    cudaFuncSetAttribute(indgru_gemm_mma,
                         cudaFuncAttributeMaxDynamicSharedMemorySize, GEMM_SMEM);
    dim3 grid(M_DIM / GBM, N_DIM / GBN);   // 128 x 12
    indgru_gemm_mma<<<grid, 256, GEMM_SMEM>>>();

    indgru_scan<<<(B_DIM * H_DIM) / 32, 32>>>(h0, w_hh, out);
}